// round 11
// baseline (speedup 1.0000x reference)
#include <cuda_runtime.h>

// Pooling_83141976916902: out[g, c] = sum_{i : batch[i]==g} x[i, c]
// (softmax over a size-1 axis == 1.0, so W/b are dead inputs)
//
// x:     [N, 128] float32   (d_in[0])
// batch: [N]      int64/int32, SORTED, values in [0, G)  (d_in[1])
// out:   [G, 128] float32
//
// At the HBM ceiling: 525MB compulsory / ~6.9TB/s. R10 change vs R8:
// 4 warps/block x 64 rows/warp (grid unchanged at 3907) -> flush count
// drops 41K -> 25.6K (L2 RMW 21MB -> 13MB), reducing the only traffic
// that competes with the x stream. Everything else identical to R8.

#define C 128
#define WARPS_PER_BLOCK 4
#define ROWS_PER_WARP 64
#define ROWS_PER_BLOCK (WARPS_PER_BLOCK * ROWS_PER_WARP)  // 256
#define THREADS (WARPS_PER_BLOCK * 32)                    // 128

// One vector reduction (REDG.128, no return) per lane. 16B-aligned by
// construction: out + seg*512B + lane*16B.
__device__ __forceinline__ void flush_acc(float* __restrict__ out, int seg,
                                          int lane, float4& acc) {
    float* o = out + (size_t)seg * C + lane * 4;
    asm volatile("red.global.add.v4.f32 [%0], {%1, %2, %3, %4};"
                 :: "l"(o), "f"(acc.x), "f"(acc.y), "f"(acc.z), "f"(acc.w)
                 : "memory");
    acc = make_float4(0.f, 0.f, 0.f, 0.f);
}

// Segmented sum. One warp owns 64 contiguous rows (two 32-row halves).
// Lane l holds channels [4l,4l+4) as a float4 accumulator (one coalesced
// 512B row read). Segment ids are loaded once per half into registers (one
// per lane) and broadcast per-row via shfl; x rows stream as front-batched
// groups of 8 independent LDG.128 (evict-first). cur/acc carry across the
// halves so boundary-spanning segments flush once.
__global__ __launch_bounds__(THREADS)
void segsum_kernel(const float4* __restrict__ x4,
                   const void* __restrict__ batch_raw,
                   float* __restrict__ out,
                   int n_rows) {
    const int warp = threadIdx.x >> 5;
    const int lane = threadIdx.x & 31;
    const int rstart = blockIdx.x * ROWS_PER_BLOCK + warp * ROWS_PER_WARP;
    if (rstart >= n_rows) return;

    // In-kernel dtype probe: highest ODD 32-bit word of the batch buffer.
    // int64 (values < 2^31): odd words are high halves -> 0.
    // int32: that word is a sorted id near the end (~G-1) -> nonzero.
    const int* __restrict__ bwords = (const int*)batch_raw;
    int pidx = ((n_rows - 1) & 1) ? (n_rows - 1) : (n_rows - 2);
    if (pidx < 0) pidx = 0;
    const bool is64 = (__ldg(&bwords[pidx]) == 0);

    const long long* __restrict__ b64 = (const long long*)batch_raw;
    const int* __restrict__ b32 = (const int*)batch_raw;

    float4 acc = make_float4(0.f, 0.f, 0.f, 0.f);

    if (rstart + ROWS_PER_WARP <= n_rows) {
        // ---- fast path: full 64-row stripe as two 32-row halves ----
        int cur = is64 ? (int)b64[rstart] : b32[rstart];
        cur = __shfl_sync(0xFFFFFFFFu, cur, 0);

#pragma unroll
        for (int h = 0; h < 2; h++) {
            const int hstart = rstart + h * 32;
            const int r_lane = hstart + lane;
            const int my_id = is64 ? (int)b64[r_lane] : b32[r_lane];

            const float4* __restrict__ p = x4 + (size_t)hstart * (C / 4) + lane;

#pragma unroll
            for (int g = 0; g < 4; g++) {
                // front-batch 8 independent 16B streaming loads (MLP_p1 = 8)
                float4 v0 = __ldcs(p + (g * 8 + 0) * (C / 4));
                float4 v1 = __ldcs(p + (g * 8 + 1) * (C / 4));
                float4 v2 = __ldcs(p + (g * 8 + 2) * (C / 4));
                float4 v3 = __ldcs(p + (g * 8 + 3) * (C / 4));
                float4 v4 = __ldcs(p + (g * 8 + 4) * (C / 4));
                float4 v5 = __ldcs(p + (g * 8 + 5) * (C / 4));
                float4 v6 = __ldcs(p + (g * 8 + 6) * (C / 4));
                float4 v7 = __ldcs(p + (g * 8 + 7) * (C / 4));

                float4 vv[8] = {v0, v1, v2, v3, v4, v5, v6, v7};
#pragma unroll
                for (int j = 0; j < 8; j++) {
                    const int s = __shfl_sync(0xFFFFFFFFu, my_id, g * 8 + j);
                    if (s != cur) {
                        flush_acc(out, cur, lane, acc);
                        cur = s;
                    }
                    acc.x += vv[j].x;
                    acc.y += vv[j].y;
                    acc.z += vv[j].z;
                    acc.w += vv[j].w;
                }
            }
        }
        flush_acc(out, cur, lane, acc);
    } else {
        // ---- generic tail path ----
        const int rend = n_rows;
        int cur = is64 ? (int)b64[rstart] : b32[rstart];
        for (int r = rstart; r < rend; r++) {
            const int s = is64 ? (int)b64[r] : b32[r];
            const float4 v = __ldcs(x4 + (size_t)r * (C / 4) + lane);
            if (s != cur) {
                flush_acc(out, cur, lane, acc);
                cur = s;
            }
            acc.x += v.x;
            acc.y += v.y;
            acc.z += v.z;
            acc.w += v.w;
        }
        flush_acc(out, cur, lane, acc);
    }
}

extern "C" void kernel_launch(void* const* d_in, const int* in_sizes, int n_in,
                              void* d_out, int out_size) {
    const float* x = (const float*)d_in[0];
    const void* batch = d_in[1];
    (void)n_in;

    const int n_rows = in_sizes[1];

    // Zero the poisoned output: graph-capturable memset node.
    cudaMemsetAsync(d_out, 0, (size_t)out_size * sizeof(float), 0);

    int blocks = (n_rows + ROWS_PER_BLOCK - 1) / ROWS_PER_BLOCK;
    segsum_kernel<<<blocks, THREADS>>>(
        (const float4*)x, batch, (float*)d_out, n_rows);
}

// round 12
// speedup vs baseline: 1.0575x; 1.0575x over previous
#include <cuda_runtime.h>

// Pooling_83141976916902: out[g, c] = sum_{i : batch[i]==g} x[i, c]
// (softmax over a size-1 axis == 1.0, so W/b are dead inputs)
//
// x:     [N, 128] float32   (d_in[0])
// batch: [N]      int64/int32, SORTED, values in [0, G)  (d_in[1])
// out:   [G, 128] float32
//
// Proven-optimal structure (R8, at the HBM wall: 525MB compulsory traffic,
// kernel time == bytes / 6.94TB/s): 32 rows/warp, 8 warps/block, ids in
// registers + shfl broadcast, 8-deep front-batched evict-first LDG.128
// stream, red.global.add.v4.f32 flush on segment change, graph memset node
// for the poisoned output.
// R12 change: dtype probe and BOTH candidate id loads (int32/int64
// interpretation) issue in parallel; select after. Removes ~240cyc of
// serial L2 latency from every block start.

#define C 128
#define WARPS_PER_BLOCK 8
#define ROWS_PER_WARP 32
#define ROWS_PER_BLOCK (WARPS_PER_BLOCK * ROWS_PER_WARP)  // 256

// One vector reduction (REDG.128, no return) per lane. 16B-aligned by
// construction: out + seg*512B + lane*16B.
__device__ __forceinline__ void flush_acc(float* __restrict__ out, int seg,
                                          int lane, float4& acc) {
    float* o = out + (size_t)seg * C + lane * 4;
    asm volatile("red.global.add.v4.f32 [%0], {%1, %2, %3, %4};"
                 :: "l"(o), "f"(acc.x), "f"(acc.y), "f"(acc.z), "f"(acc.w)
                 : "memory");
    acc = make_float4(0.f, 0.f, 0.f, 0.f);
}

__global__ __launch_bounds__(ROWS_PER_BLOCK)
void segsum_kernel(const float4* __restrict__ x4,
                   const void* __restrict__ batch_raw,
                   float* __restrict__ out,
                   int n_rows) {
    const int warp = threadIdx.x >> 5;
    const int lane = threadIdx.x & 31;
    const int rstart = blockIdx.x * ROWS_PER_BLOCK + warp * ROWS_PER_WARP;
    if (rstart >= n_rows) return;

    const int* __restrict__ bwords = (const int*)batch_raw;
    const long long* __restrict__ b64 = (const long long*)batch_raw;
    const int* __restrict__ b32 = (const int*)batch_raw;

    float4 acc = make_float4(0.f, 0.f, 0.f, 0.f);

    if (rstart + ROWS_PER_WARP <= n_rows) {
        // ---- fast path: full 32-row stripe (always taken when N % 32 == 0) ----
        const int r_lane = rstart + lane;

        // Issue probe + BOTH dtype interpretations' id loads concurrently
        // (three independent loads in flight; select once probe lands).
        // Probe: highest ODD 32-bit word. int64 high-half -> 0; int32
        // payload is a sorted id near the end (~G-1) -> nonzero.
        int pidx = ((n_rows - 1) & 1) ? (n_rows - 1) : (n_rows - 2);
        if (pidx < 0) pidx = 0;
        const int probe = __ldg(&bwords[pidx]);
        const int id32 = __ldg(&b32[r_lane]);
        const int id64 = (int)__ldg(&b64[r_lane]);
        const int my_id = (probe == 0) ? id64 : id32;

        const float4* __restrict__ p = x4 + (size_t)rstart * (C / 4) + lane;
        int cur = __shfl_sync(0xFFFFFFFFu, my_id, 0);

#pragma unroll
        for (int g = 0; g < ROWS_PER_WARP / 8; g++) {
            // front-batch 8 independent 16B streaming loads (MLP_p1 = 8)
            float4 v0 = __ldcs(p + (g * 8 + 0) * (C / 4));
            float4 v1 = __ldcs(p + (g * 8 + 1) * (C / 4));
            float4 v2 = __ldcs(p + (g * 8 + 2) * (C / 4));
            float4 v3 = __ldcs(p + (g * 8 + 3) * (C / 4));
            float4 v4 = __ldcs(p + (g * 8 + 4) * (C / 4));
            float4 v5 = __ldcs(p + (g * 8 + 5) * (C / 4));
            float4 v6 = __ldcs(p + (g * 8 + 6) * (C / 4));
            float4 v7 = __ldcs(p + (g * 8 + 7) * (C / 4));

            float4 vv[8] = {v0, v1, v2, v3, v4, v5, v6, v7};
#pragma unroll
            for (int j = 0; j < 8; j++) {
                const int s = __shfl_sync(0xFFFFFFFFu, my_id, g * 8 + j);
                if (s != cur) {
                    flush_acc(out, cur, lane, acc);
                    cur = s;
                }
                acc.x += vv[j].x;
                acc.y += vv[j].y;
                acc.z += vv[j].z;
                acc.w += vv[j].w;
            }
        }
        flush_acc(out, cur, lane, acc);
    } else {
        // ---- generic tail path ----
        int pidx = ((n_rows - 1) & 1) ? (n_rows - 1) : (n_rows - 2);
        if (pidx < 0) pidx = 0;
        const bool is64 = (__ldg(&bwords[pidx]) == 0);

        const int rend = n_rows;
        int cur = is64 ? (int)b64[rstart] : b32[rstart];
        for (int r = rstart; r < rend; r++) {
            const int s = is64 ? (int)b64[r] : b32[r];
            const float4 v = __ldcs(x4 + (size_t)r * (C / 4) + lane);
            if (s != cur) {
                flush_acc(out, cur, lane, acc);
                cur = s;
            }
            acc.x += v.x;
            acc.y += v.y;
            acc.z += v.z;
            acc.w += v.w;
        }
        flush_acc(out, cur, lane, acc);
    }
}

extern "C" void kernel_launch(void* const* d_in, const int* in_sizes, int n_in,
                              void* d_out, int out_size) {
    const float* x = (const float*)d_in[0];
    const void* batch = d_in[1];
    (void)n_in;

    const int n_rows = in_sizes[1];

    // Zero the poisoned output: graph-capturable memset node.
    cudaMemsetAsync(d_out, 0, (size_t)out_size * sizeof(float), 0);

    int blocks = (n_rows + ROWS_PER_BLOCK - 1) / ROWS_PER_BLOCK;
    segsum_kernel<<<blocks, ROWS_PER_BLOCK>>>(
        (const float4*)x, batch, (float*)d_out, n_rows);
}